// round 15
// baseline (speedup 1.0000x reference)
#include <cuda_runtime.h>
#include <math_constants.h>

#define V 32000
#define T 128
#define E 64
#define NN 1024

#define BOUND 1.4142135623730951f
#define LSMIN -2.302585092994046f
#define LSMAX 2.302585092994046f
#define LN2F  0.6931471805599453f

// scratch: logits -> softmax weights, stored transposed [T][V]
__device__ float g_wT[(size_t)T * V];

__device__ __forceinline__ float frcp(float x) {
    float r; asm("rcp.approx.ftz.f32 %0, %1;" : "=f"(r) : "f"(x)); return r;
}

typedef unsigned long long u64;
__device__ __forceinline__ u64 pack2(float a) {
    u64 r; asm("mov.b64 %0, {%1, %1};" : "=l"(r) : "f"(a)); return r;
}
__device__ __forceinline__ u64 pk(float x, float y) {
    u64 r; asm("mov.b64 %0, {%1, %2};" : "=l"(r) : "f"(x), "f"(y)); return r;
}
__device__ __forceinline__ void upk(u64 v, float& x, float& y) {
    asm("mov.b64 {%0, %1}, %2;" : "=f"(x), "=f"(y) : "l"(v));
}
__device__ __forceinline__ u64 ffma2(u64 a, u64 b, u64 c) {
    u64 d; asm("fma.rn.f32x2 %0, %1, %2, %3;" : "=l"(d) : "l"(a), "l"(b), "l"(c)); return d;
}

// ---------------------------------------------------------------------------
// Stage 1: energy logits.  Block = 32 vocab rows x all 128 topics.
// Warp handles (v, 32 topics); lane = topic. Quad trick: 1 RCP / 4 elems,
// 1 LG2 / 8 elems. Writes transposed [T][V] via padded staging tile.
// ---------------------------------------------------------------------------
__global__ void __launch_bounds__(256, 2) energy_kernel(
    const float* __restrict__ mu, const float* __restrict__ ls,
    const float* __restrict__ muc, const float* __restrict__ lsc)
{
    extern __shared__ float sm[];
    float* sc    = sm;          // [128][64] sigma_c, xor-swizzled float4 rows
    float* mc    = sm + 8192;   // [128][64] mu_c,    xor-swizzled
    float* sv    = sm + 16384;  // [32][64] sigma_v (broadcast reads)
    float* mv    = sm + 18432;  // [32][64] mu_v
    float* stage = sm + 20480;  // [32][129] logit staging (pad 1)

    const int tid = threadIdx.x;
    const int vbase = blockIdx.x << 5;

    // fill context params (clamp + exp), swizzled for conflict-free LDS.128
    for (int i = tid; i < T * E; i += 256) {
        int t = i >> 6, e = i & 63;
        int sw = (t << 6) | ((((e >> 2) ^ (t & 15)) << 2) | (e & 3));
        sc[sw] = __expf(fminf(fmaxf(lsc[i], LSMIN), LSMAX));
        mc[sw] = fminf(fmaxf(muc[i], -BOUND), BOUND);
    }
    // fill this block's 32 vocab rows
    for (int i = tid; i < 32 * E; i += 256) {
        int gi = vbase * E + i;
        sv[i] = __expf(fminf(fmaxf(ls[gi], LSMIN), LSMAX));
        mv[i] = fminf(fmaxf(mu[gi], -BOUND), BOUND);
    }
    __syncthreads();

    const int warp = tid >> 5, lane = tid & 31;
    for (int it = 0; it < 16; ++it) {
        int task = (it << 3) | warp;      // 0..127
        int vl = task >> 2;               // 0..31
        int t = ((task & 3) << 5) | lane; // 0..127
        const float4* scr = (const float4*)(sc + (t << 6));
        const float4* mcr = (const float4*)(mc + (t << 6));
        const float4* svr = (const float4*)(sv + (vl << 6));
        const float4* mvr = (const float4*)(mv + (vl << 6));
        const int key = t & 15;
        float acc = 0.f, lg = 0.f;
        #pragma unroll
        for (int g = 0; g < 8; ++g) {
            float p8 = 1.f;
            #pragma unroll
            for (int h = 0; h < 2; ++h) {
                const int e4 = (g << 1) | h;
                float4 s4 = scr[e4 ^ key];
                float4 c4 = mcr[e4 ^ key];
                float4 a4 = svr[e4];
                float4 m4 = mvr[e4];
                float s0 = a4.x + s4.x, s1 = a4.y + s4.y;
                float s2 = a4.z + s4.z, s3 = a4.w + s4.w;
                float d0 = m4.x - c4.x, d1 = m4.y - c4.y;
                float d2 = m4.z - c4.z, d3 = m4.w - c4.w;
                float q01 = s0 * s1, q23 = s2 * s3;
                // d0^2/s0 + d1^2/s1 + d2^2/s2 + d3^2/s3 = num / (q01*q23)
                float n01 = fmaf(d1 * d1, s0, (d0 * d0) * s1);
                float n23 = fmaf(d3 * d3, s2, (d2 * d2) * s3);
                float num = fmaf(n23, q01, n01 * q23);
                float p4 = q01 * q23;
                acc = fmaf(num, frcp(p4), acc);
                p8 = h ? (p8 * p4) : p4;
            }
            lg += __log2f(p8);  // sum ln(s_e) over 8 elems; safe range
        }
        // drop constant E*ln(2pi): cancels in softmax over v
        stage[vl * 129 + t] = -0.5f * fmaf(lg, LN2F, acc);
    }
    __syncthreads();

    // coalesced transpose-out: g_wT[t][vbase + vl]
    for (int j = tid; j < 32 * T; j += 256) {
        int t = j >> 5, vl = j & 31;
        g_wT[(size_t)t * V + vbase + vl] = stage[vl * 129 + t];
    }
}

// ---------------------------------------------------------------------------
// Stage 2: per-topic softmax over the V axis. One block per topic row;
// rows are contiguous (transposed layout) -> fully coalesced float4 sweeps.
// ---------------------------------------------------------------------------
__global__ void __launch_bounds__(256) softmax_kernel()
{
    const int t = blockIdx.x;
    float4* r4 = (float4*)(g_wT + (size_t)t * V);
    __shared__ float sred[8];
    __shared__ float sbc[2];
    const int tid = threadIdx.x, lane = tid & 31, w = tid >> 5;

    float m = -CUDART_INF_F;
    for (int i = tid; i < V / 4; i += 256) {
        float4 v = r4[i];
        m = fmaxf(m, fmaxf(fmaxf(v.x, v.y), fmaxf(v.z, v.w)));
    }
    #pragma unroll
    for (int o = 16; o; o >>= 1) m = fmaxf(m, __shfl_xor_sync(0xffffffffu, m, o));
    if (lane == 0) sred[w] = m;
    __syncthreads();
    if (tid == 0) {
        float mm = sred[0];
        #pragma unroll
        for (int i = 1; i < 8; ++i) mm = fmaxf(mm, sred[i]);
        sbc[0] = mm;
    }
    __syncthreads();
    m = sbc[0];

    float s = 0.f;
    for (int i = tid; i < V / 4; i += 256) {
        float4 v = r4[i];
        s += __expf(v.x - m) + __expf(v.y - m) + __expf(v.z - m) + __expf(v.w - m);
    }
    #pragma unroll
    for (int o = 16; o; o >>= 1) s += __shfl_xor_sync(0xffffffffu, s, o);
    if (lane == 0) sred[w] = s;
    __syncthreads();
    if (tid == 0) {
        float ss = 0.f;
        #pragma unroll
        for (int i = 0; i < 8; ++i) ss += sred[i];
        sbc[1] = 1.0f / ss;
    }
    __syncthreads();
    const float rz = sbc[1];

    for (int i = tid; i < V / 4; i += 256) {
        float4 v = r4[i];
        v.x = __expf(v.x - m) * rz;
        v.y = __expf(v.y - m) * rz;
        v.z = __expf(v.z - m) * rz;
        v.w = __expf(v.w - m) * rz;
        r4[i] = v;
    }
}

// ---------------------------------------------------------------------------
// Stage 3: out[V][N] = w^T[T][V]^T @ x[T][N].  K = T = 128 -> single tile,
// no k-pipeline. 128x128 block tile, 8x8 micro-tile, packed fma.rn.f32x2
// (2 MACs/inst). A LDS conflict-free, B LDS broadcast, 32B stores per lane.
// ---------------------------------------------------------------------------
__global__ void __launch_bounds__(256, 1) gemm_kernel(
    const float* __restrict__ x, float* __restrict__ out)
{
    extern __shared__ float sm[];
    float4* As = (float4*)sm;               // [128][32] f4 : (t, v/4)
    float4* Bs = (float4*)(sm + 128 * 128); // [128][32] f4 : (t, n/4)
    const int tid = threadIdx.x;
    const int vbase = blockIdx.x << 7;
    const int nbase = blockIdx.y << 7;

    const float4* gA = (const float4*)(g_wT + vbase);
    const float4* gB = (const float4*)(x + nbase);
    for (int j = tid; j < 128 * 32; j += 256) {
        int t = j >> 5, c = j & 31;
        As[j] = gA[(size_t)t * (V / 4) + c];
        Bs[j] = gB[t * (NN / 4) + c];
    }
    __syncthreads();

    const int tm = tid & 15;  // v strips: tm*4 and 64+tm*4
    const int tn = tid >> 4;  // n strip: tn*8 (contiguous 32B per lane)

    u64 acc[8][4];
    #pragma unroll
    for (int i = 0; i < 8; ++i)
        #pragma unroll
        for (int j = 0; j < 4; ++j) acc[i][j] = 0ull;

    #pragma unroll 4
    for (int k = 0; k < 128; ++k) {
        float4 a0 = As[(k << 5) + tm];
        float4 a1 = As[(k << 5) + 16 + tm];
        float4 b0 = Bs[(k << 5) + (tn << 1)];
        float4 b1 = Bs[(k << 5) + (tn << 1) + 1];
        u64 B[4] = { pk(b0.x, b0.y), pk(b0.z, b0.w), pk(b1.x, b1.y), pk(b1.z, b1.w) };
        float av[8] = { a0.x, a0.y, a0.z, a0.w, a1.x, a1.y, a1.z, a1.w };
        #pragma unroll
        for (int i = 0; i < 8; ++i) {
            u64 aa = pack2(av[i]);
            #pragma unroll
            for (int j = 0; j < 4; ++j) acc[i][j] = ffma2(aa, B[j], acc[i][j]);
        }
    }

    #pragma unroll
    for (int i = 0; i < 8; ++i) {
        int vv = vbase + ((i < 4) ? (tm * 4 + i) : (64 + tm * 4 + (i - 4)));
        float* orow = out + (size_t)vv * NN + nbase + (tn << 3);
        float4 o0, o1;
        upk(acc[i][0], o0.x, o0.y); upk(acc[i][1], o0.z, o0.w);
        upk(acc[i][2], o1.x, o1.y); upk(acc[i][3], o1.z, o1.w);
        ((float4*)orow)[0] = o0;
        ((float4*)orow)[1] = o1;
    }
}

// ---------------------------------------------------------------------------
extern "C" void kernel_launch(void* const* d_in, const int* in_sizes, int n_in,
                              void* d_out, int out_size)
{
    const float* x   = (const float*)d_in[0];  // [T, N]
    const float* mu  = (const float*)d_in[1];  // [V, E]
    const float* ls  = (const float*)d_in[2];  // [V, E]
    const float* muc = (const float*)d_in[3];  // [T, E]
    const float* lsc = (const float*)d_in[4];  // [T, E]
    float* out = (float*)d_out;                // [V, N]

    const int energy_smem = 24608 * 4;     // 96.1 KB
    const int gemm_smem   = 128 * 128 * 2 * 4;  // 128 KB
    cudaFuncSetAttribute(energy_kernel, cudaFuncAttributeMaxDynamicSharedMemorySize, energy_smem);
    cudaFuncSetAttribute(gemm_kernel,   cudaFuncAttributeMaxDynamicSharedMemorySize, gemm_smem);

    energy_kernel<<<V / 32, 256, energy_smem>>>(mu, ls, muc, lsc);
    softmax_kernel<<<T, 256>>>();
    gemm_kernel<<<dim3(V / 128, NN / 128), 256, gemm_smem>>>(x, out);
}

// round 16
// speedup vs baseline: 1.5561x; 1.5561x over previous
#include <cuda_runtime.h>
#include <math_constants.h>

#define V 32000
#define T 128
#define E 64
#define NN 1024

#define BOUND 1.4142135623730951f
#define LSMIN -2.302585092994046f
#define LSMAX 2.302585092994046f
#define LN2F  0.6931471805599453f

// scratch: logits -> softmax weights, stored transposed [T][V]
__device__ float g_wT[(size_t)T * V];

__device__ __forceinline__ float frcp(float x) {
    float r; asm("rcp.approx.ftz.f32 %0, %1;" : "=f"(r) : "f"(x)); return r;
}

typedef unsigned long long u64;
__device__ __forceinline__ u64 pack2(float a) {
    u64 r; asm("mov.b64 %0, {%1, %1};" : "=l"(r) : "f"(a)); return r;
}
__device__ __forceinline__ u64 pk(float x, float y) {
    u64 r; asm("mov.b64 %0, {%1, %2};" : "=l"(r) : "f"(x), "f"(y)); return r;
}
__device__ __forceinline__ void upk(u64 v, float& x, float& y) {
    asm("mov.b64 {%0, %1}, %2;" : "=f"(x), "=f"(y) : "l"(v));
}
__device__ __forceinline__ u64 ffma2(u64 a, u64 b, u64 c) {
    u64 d; asm("fma.rn.f32x2 %0, %1, %2, %3;" : "=l"(d) : "l"(a), "l"(b), "l"(c)); return d;
}

// ---------------------------------------------------------------------------
// Stage 1: energy logits.  Block = 32 vocab rows x all 128 topics.
// Warp handles (v, 32 topics); lane = topic. Quad trick: 1 RCP / 4 elems,
// 1 LG2 / 8 elems. Writes transposed [T][V] via padded staging tile.
// ---------------------------------------------------------------------------
__global__ void __launch_bounds__(256, 2) energy_kernel(
    const float* __restrict__ mu, const float* __restrict__ ls,
    const float* __restrict__ muc, const float* __restrict__ lsc)
{
    extern __shared__ float sm[];
    float* sc    = sm;          // [128][64] sigma_c, xor-swizzled float4 rows
    float* mc    = sm + 8192;   // [128][64] mu_c,    xor-swizzled
    float* sv    = sm + 16384;  // [32][64] sigma_v (broadcast reads)
    float* mv    = sm + 18432;  // [32][64] mu_v
    float* stage = sm + 20480;  // [32][129] logit staging (pad 1)

    const int tid = threadIdx.x;
    const int vbase = blockIdx.x << 5;

    // fill context params (clamp + exp), swizzled for conflict-free LDS.128
    for (int i = tid; i < T * E; i += 256) {
        int t = i >> 6, e = i & 63;
        int sw = (t << 6) | ((((e >> 2) ^ (t & 15)) << 2) | (e & 3));
        sc[sw] = __expf(fminf(fmaxf(lsc[i], LSMIN), LSMAX));
        mc[sw] = fminf(fmaxf(muc[i], -BOUND), BOUND);
    }
    // fill this block's 32 vocab rows
    for (int i = tid; i < 32 * E; i += 256) {
        int gi = vbase * E + i;
        sv[i] = __expf(fminf(fmaxf(ls[gi], LSMIN), LSMAX));
        mv[i] = fminf(fmaxf(mu[gi], -BOUND), BOUND);
    }
    __syncthreads();

    const int warp = tid >> 5, lane = tid & 31;
    for (int it = 0; it < 16; ++it) {
        int task = (it << 3) | warp;      // 0..127
        int vl = task >> 2;               // 0..31
        int t = ((task & 3) << 5) | lane; // 0..127
        const float4* scr = (const float4*)(sc + (t << 6));
        const float4* mcr = (const float4*)(mc + (t << 6));
        const float4* svr = (const float4*)(sv + (vl << 6));
        const float4* mvr = (const float4*)(mv + (vl << 6));
        const int key = t & 15;
        float acc = 0.f, lg = 0.f;
        #pragma unroll
        for (int g = 0; g < 8; ++g) {
            float p8 = 1.f;
            #pragma unroll
            for (int h = 0; h < 2; ++h) {
                const int e4 = (g << 1) | h;
                float4 s4 = scr[e4 ^ key];
                float4 c4 = mcr[e4 ^ key];
                float4 a4 = svr[e4];
                float4 m4 = mvr[e4];
                float s0 = a4.x + s4.x, s1 = a4.y + s4.y;
                float s2 = a4.z + s4.z, s3 = a4.w + s4.w;
                float d0 = m4.x - c4.x, d1 = m4.y - c4.y;
                float d2 = m4.z - c4.z, d3 = m4.w - c4.w;
                float q01 = s0 * s1, q23 = s2 * s3;
                // d0^2/s0 + d1^2/s1 + d2^2/s2 + d3^2/s3 = num / (q01*q23)
                float n01 = fmaf(d1 * d1, s0, (d0 * d0) * s1);
                float n23 = fmaf(d3 * d3, s2, (d2 * d2) * s3);
                float num = fmaf(n23, q01, n01 * q23);
                float p4 = q01 * q23;
                acc = fmaf(num, frcp(p4), acc);
                p8 = h ? (p8 * p4) : p4;
            }
            lg += __log2f(p8);  // sum ln(s_e) over 8 elems; safe range
        }
        // drop constant E*ln(2pi): cancels in softmax over v
        stage[vl * 129 + t] = -0.5f * fmaf(lg, LN2F, acc);
    }
    __syncthreads();

    // coalesced transpose-out: g_wT[t][vbase + vl]
    for (int j = tid; j < 32 * T; j += 256) {
        int t = j >> 5, vl = j & 31;
        g_wT[(size_t)t * V + vbase + vl] = stage[vl * 129 + t];
    }
}

// ---------------------------------------------------------------------------
// Stage 2: per-topic softmax over the V axis. One block per topic row;
// rows are contiguous (transposed layout) -> fully coalesced float4 sweeps.
// ---------------------------------------------------------------------------
__global__ void __launch_bounds__(256) softmax_kernel()
{
    const int t = blockIdx.x;
    float4* r4 = (float4*)(g_wT + (size_t)t * V);
    __shared__ float sred[8];
    __shared__ float sbc[2];
    const int tid = threadIdx.x, lane = tid & 31, w = tid >> 5;

    float m = -CUDART_INF_F;
    for (int i = tid; i < V / 4; i += 256) {
        float4 v = r4[i];
        m = fmaxf(m, fmaxf(fmaxf(v.x, v.y), fmaxf(v.z, v.w)));
    }
    #pragma unroll
    for (int o = 16; o; o >>= 1) m = fmaxf(m, __shfl_xor_sync(0xffffffffu, m, o));
    if (lane == 0) sred[w] = m;
    __syncthreads();
    if (tid == 0) {
        float mm = sred[0];
        #pragma unroll
        for (int i = 1; i < 8; ++i) mm = fmaxf(mm, sred[i]);
        sbc[0] = mm;
    }
    __syncthreads();
    m = sbc[0];

    float s = 0.f;
    for (int i = tid; i < V / 4; i += 256) {
        float4 v = r4[i];
        s += __expf(v.x - m) + __expf(v.y - m) + __expf(v.z - m) + __expf(v.w - m);
    }
    #pragma unroll
    for (int o = 16; o; o >>= 1) s += __shfl_xor_sync(0xffffffffu, s, o);
    if (lane == 0) sred[w] = s;
    __syncthreads();
    if (tid == 0) {
        float ss = 0.f;
        #pragma unroll
        for (int i = 0; i < 8; ++i) ss += sred[i];
        sbc[1] = 1.0f / ss;
    }
    __syncthreads();
    const float rz = sbc[1];

    for (int i = tid; i < V / 4; i += 256) {
        float4 v = r4[i];
        v.x = __expf(v.x - m) * rz;
        v.y = __expf(v.y - m) * rz;
        v.z = __expf(v.z - m) * rz;
        v.w = __expf(v.w - m) * rz;
        r4[i] = v;
    }
}

// ---------------------------------------------------------------------------
// Stage 3: out[V][N] = w^T[T][V]^T @ x[T][N].  K = T = 128 -> single tile,
// no k-pipeline. 128x128 block tile, 8x8 micro-tile, packed fma.rn.f32x2
// (2 MACs/inst). A LDS conflict-free, B LDS broadcast, 32B stores per lane.
// ---------------------------------------------------------------------------
__global__ void __launch_bounds__(256, 1) gemm_kernel(
    const float* __restrict__ x, float* __restrict__ out)
{
    extern __shared__ float sm[];
    float4* As = (float4*)sm;               // [128][32] f4 : (t, v/4)
    float4* Bs = (float4*)(sm + 128 * 128); // [128][32] f4 : (t, n/4)
    const int tid = threadIdx.x;
    const int vbase = blockIdx.x << 7;
    const int nbase = blockIdx.y << 7;

    const float4* gA = (const float4*)(g_wT + vbase);
    const float4* gB = (const float4*)(x + nbase);
    for (int j = tid; j < 128 * 32; j += 256) {
        int t = j >> 5, c = j & 31;
        As[j] = gA[(size_t)t * (V / 4) + c];
        Bs[j] = gB[t * (NN / 4) + c];
    }
    __syncthreads();

    const int tm = tid & 15;  // v strips: tm*4 and 64+tm*4
    const int tn = tid >> 4;  // n strip: tn*8 (contiguous 32B per lane)

    u64 acc[8][4];
    #pragma unroll
    for (int i = 0; i < 8; ++i)
        #pragma unroll
        for (int j = 0; j < 4; ++j) acc[i][j] = 0ull;

    #pragma unroll 4
    for (int k = 0; k < 128; ++k) {
        float4 a0 = As[(k << 5) + tm];
        float4 a1 = As[(k << 5) + 16 + tm];
        float4 b0 = Bs[(k << 5) + (tn << 1)];
        float4 b1 = Bs[(k << 5) + (tn << 1) + 1];
        u64 B[4] = { pk(b0.x, b0.y), pk(b0.z, b0.w), pk(b1.x, b1.y), pk(b1.z, b1.w) };
        float av[8] = { a0.x, a0.y, a0.z, a0.w, a1.x, a1.y, a1.z, a1.w };
        #pragma unroll
        for (int i = 0; i < 8; ++i) {
            u64 aa = pack2(av[i]);
            #pragma unroll
            for (int j = 0; j < 4; ++j) acc[i][j] = ffma2(aa, B[j], acc[i][j]);
        }
    }

    #pragma unroll
    for (int i = 0; i < 8; ++i) {
        int vv = vbase + ((i < 4) ? (tm * 4 + i) : (64 + tm * 4 + (i - 4)));
        float* orow = out + (size_t)vv * NN + nbase + (tn << 3);
        float4 o0, o1;
        upk(acc[i][0], o0.x, o0.y); upk(acc[i][1], o0.z, o0.w);
        upk(acc[i][2], o1.x, o1.y); upk(acc[i][3], o1.z, o1.w);
        ((float4*)orow)[0] = o0;
        ((float4*)orow)[1] = o1;
    }
}

// ---------------------------------------------------------------------------
extern "C" void kernel_launch(void* const* d_in, const int* in_sizes, int n_in,
                              void* d_out, int out_size)
{
    const float* x   = (const float*)d_in[0];  // [T, N]
    const float* mu  = (const float*)d_in[1];  // [V, E]
    const float* ls  = (const float*)d_in[2];  // [V, E]
    const float* muc = (const float*)d_in[3];  // [T, E]
    const float* lsc = (const float*)d_in[4];  // [T, E]
    float* out = (float*)d_out;                // [V, N]

    const int energy_smem = 24608 * 4;     // 96.1 KB
    const int gemm_smem   = 128 * 128 * 2 * 4;  // 128 KB
    cudaFuncSetAttribute(energy_kernel, cudaFuncAttributeMaxDynamicSharedMemorySize, energy_smem);
    cudaFuncSetAttribute(gemm_kernel,   cudaFuncAttributeMaxDynamicSharedMemorySize, gemm_smem);

    energy_kernel<<<V / 32, 256, energy_smem>>>(mu, ls, muc, lsc);
    softmax_kernel<<<T, 256>>>();
    gemm_kernel<<<dim3(V / 128, NN / 128), 256, gemm_smem>>>(x, out);
}